// round 1
// baseline (speedup 1.0000x reference)
#include <cuda_runtime.h>
#include <math.h>
#include <float.h>

#define Bc 4
#define Lc 1024
#define Hc 12
#define Ec 64
#define BM 64
#define BN 64
#define NTHR 256

// 12 MB scratch for qhat (allocation-free rule: __device__ global)
__device__ float g_qhat[Bc * Lc * Hc * Ec];

// XOR-swizzled smem layout at 16B-chunk granularity:
// tile is [64 rows][16 chunks of float4]; returns FLOAT offset.
__device__ __forceinline__ int sw(int row, int c4) {
    return (row * 16 + (c4 ^ (row & 15))) * 4;
}

// ---------------------------------------------------------------------------
// Stage 1: per-(b,h) prefix softmax scan producing qhat[b,i,h,:]
// grid = B*H blocks, 1024 threads
// ---------------------------------------------------------------------------
__global__ void __launch_bounds__(1024) stage1_kernel(
    const float* __restrict__ q, const float* __restrict__ wv,
    const float* __restrict__ q_mask, float* __restrict__ qhat)
{
    int bh = blockIdx.x;
    int b = bh / Hc, h = bh % Hc;

    __shared__ float s_sh[Lc];        // scores, then exp weights
    __shared__ float invZ[Lc];
    __shared__ float gsum[16][Ec];
    __shared__ float w_sh[Ec];
    __shared__ float red[32];
    __shared__ float Msh;

    int tid = threadIdx.x;
    int lane = tid & 31, warp = tid >> 5;

    if (tid < Ec) w_sh[tid] = wv[h * Ec + tid];
    __syncthreads();
    float qm = q_mask[b * Lc];  // q_mask[:, :1] => scalar per batch

    // --- scores s_j = (q_j . w) * qm : one warp per j ---
    for (int j = warp; j < Lc; j += 32) {
        const float* qrow = q + ((size_t)((b * Lc + j) * Hc + h)) * Ec;
        float p = qrow[lane] * w_sh[lane] + qrow[lane + 32] * w_sh[lane + 32];
        #pragma unroll
        for (int o = 16; o; o >>= 1) p += __shfl_xor_sync(0xffffffffu, p, o);
        if (lane == 0) s_sh[j] = p * qm;
    }
    __syncthreads();

    // --- global max over the sequence ---
    float m = s_sh[tid];
    #pragma unroll
    for (int o = 16; o; o >>= 1) m = fmaxf(m, __shfl_xor_sync(0xffffffffu, m, o));
    if (lane == 0) red[warp] = m;
    __syncthreads();
    if (warp == 0) {
        float t = red[lane];
        #pragma unroll
        for (int o = 16; o; o >>= 1) t = fmaxf(t, __shfl_xor_sync(0xffffffffu, t, o));
        if (lane == 0) Msh = t;
    }
    __syncthreads();
    float M = Msh;

    // --- exp weights + inclusive scan of Z ---
    float wexp = __expf(s_sh[tid] - M);
    float sc = wexp;
    #pragma unroll
    for (int o = 1; o < 32; o <<= 1) {
        float t = __shfl_up_sync(0xffffffffu, sc, o);
        if (lane >= o) sc += t;
    }
    if (lane == 31) red[warp] = sc;
    __syncthreads();
    if (warp == 0) {
        float v = red[lane];
        float scn = v;
        #pragma unroll
        for (int o = 1; o < 32; o <<= 1) {
            float t = __shfl_up_sync(0xffffffffu, scn, o);
            if (lane >= o) scn += t;
        }
        red[lane] = scn - v;  // exclusive
    }
    __syncthreads();
    float Z = sc + red[warp];
    s_sh[tid] = wexp;       // safe: each thread overwrites its own element
    invZ[tid] = 1.0f / Z;
    __syncthreads();

    // --- hierarchical vector scan: 16 groups x 64 e-threads ---
    int g = tid >> 6, e = tid & 63;
    const float* qbase = q + (((size_t)(b * Lc)) * Hc + h) * Ec + e;
    float* qhbase = qhat + (((size_t)(b * Lc)) * Hc + h) * Ec + e;
    const size_t rstride = (size_t)Hc * Ec;

    float acc = 0.f;
    int j0 = g * 64;
    #pragma unroll 4
    for (int j = j0; j < j0 + 64; ++j) acc += s_sh[j] * qbase[(size_t)j * rstride];
    gsum[g][e] = acc;
    __syncthreads();
    if (tid < 64) {
        float off = 0.f;
        #pragma unroll
        for (int gg = 0; gg < 16; ++gg) {
            float t = gsum[gg][tid];
            gsum[gg][tid] = off;
            off += t;
        }
    }
    __syncthreads();
    acc = gsum[g][e];
    #pragma unroll 4
    for (int j = j0; j < j0 + 64; ++j) {
        acc += s_sh[j] * qbase[(size_t)j * rstride];
        qhbase[(size_t)j * rstride] = acc * invZ[j];
    }
}

// ---------------------------------------------------------------------------
// Stage 2: causal flash attention, score = (2 qhat.k - |qhat|^2 - |k|^2)*km
// grid = (L/BM, B*H), 256 threads, dynamic smem 4 tiles + norms
// ---------------------------------------------------------------------------
__global__ void __launch_bounds__(NTHR) stage2_kernel(
    const float* __restrict__ q, const float* __restrict__ k,
    const float* __restrict__ v, const float* __restrict__ k_mask,
    const float* __restrict__ qhat, float* __restrict__ out)
{
    extern __shared__ float smem[];
    float* Qs = smem;                  // 64x64 swizzled
    float* Ks = Qs + BM * Ec;
    float* Vs = Ks + BN * Ec;
    float* Ps = Vs + BN * Ec;
    float* qn_sh = Ps + BM * BN;       // 64
    float* kn_sh = qn_sh + BM;         // 64

    int bh = blockIdx.y;
    int b = bh / Hc, h = bh % Hc;
    int it = (int)gridDim.x - 1 - (int)blockIdx.x;   // heavy tiles first
    int i0 = it * BM;
    int tid = threadIdx.x;
    int tc = tid & 15, tr = tid >> 4;
    float km = k_mask[b * Lc];

    // load Q tile (qhat) swizzled
    #pragma unroll
    for (int ii = 0; ii < 4; ++ii) {
        int idx = ii * 256 + tid;
        int row = idx >> 4, c4 = idx & 15;
        const float4 src = *(const float4*)(qhat +
            ((size_t)((b * Lc + i0 + row) * Hc + h)) * Ec + c4 * 4);
        *(float4*)(Qs + sw(row, c4)) = src;
    }
    __syncthreads();
    if (tid < BM) {
        float s = 0.f;
        #pragma unroll
        for (int c = 0; c < 16; ++c) {
            const float4 x = *(const float4*)(Qs + sw(tid, c));
            s += x.x * x.x + x.y * x.y + x.z * x.z + x.w * x.w;
        }
        qn_sh[tid] = s;
    }

    float o[4][4];
    float mrow[4], lrow[4];
    #pragma unroll
    for (int r = 0; r < 4; ++r) {
        mrow[r] = -INFINITY; lrow[r] = 0.f;
        #pragma unroll
        for (int c = 0; c < 4; ++c) o[r][c] = 0.f;
    }

    for (int jt = 0; jt <= it; ++jt) {
        int j0 = jt * BN;
        __syncthreads();  // protect Ks/Vs/Ps reuse + qn_sh on first iter

        // load K, V tiles swizzled
        #pragma unroll
        for (int ii = 0; ii < 4; ++ii) {
            int idx = ii * 256 + tid;
            int row = idx >> 4, c4 = idx & 15;
            size_t goff = ((size_t)((b * Lc + j0 + row) * Hc + h)) * Ec + c4 * 4;
            *(float4*)(Ks + sw(row, c4)) = *(const float4*)(k + goff);
            *(float4*)(Vs + sw(row, c4)) = *(const float4*)(v + goff);
        }
        __syncthreads();

        // S = Qhat . K^T  (4x4 per thread, float4 over e)
        float acc[4][4];
        #pragma unroll
        for (int r = 0; r < 4; ++r)
            #pragma unroll
            for (int c = 0; c < 4; ++c) acc[r][c] = 0.f;

        #pragma unroll
        for (int ee = 0; ee < 16; ++ee) {
            float4 a[4], bf[4];
            #pragma unroll
            for (int r = 0; r < 4; ++r) a[r] = *(const float4*)(Qs + sw(tr * 4 + r, ee));
            #pragma unroll
            for (int c = 0; c < 4; ++c) bf[c] = *(const float4*)(Ks + sw(tc * 4 + c, ee));
            #pragma unroll
            for (int r = 0; r < 4; ++r)
                #pragma unroll
                for (int c = 0; c < 4; ++c)
                    acc[r][c] += a[r].x * bf[c].x + a[r].y * bf[c].y
                               + a[r].z * bf[c].z + a[r].w * bf[c].w;
        }

        // key norms for this tile
        if (tid < BN) {
            float s = 0.f;
            #pragma unroll
            for (int c = 0; c < 16; ++c) {
                const float4 x = *(const float4*)(Ks + sw(tid, c));
                s += x.x * x.x + x.y * x.y + x.z * x.z + x.w * x.w;
            }
            kn_sh[tid] = s;
        }
        __syncthreads();

        // scores + online softmax (row groups = 16 lanes sharing tr)
        #pragma unroll
        for (int r = 0; r < 4; ++r) {
            int ig = i0 + tr * 4 + r;
            float qn = qn_sh[tr * 4 + r];
            float mx = -INFINITY;
            #pragma unroll
            for (int c = 0; c < 4; ++c) {
                int jg = j0 + tc * 4 + c;
                float s = (2.f * acc[r][c] - qn - kn_sh[tc * 4 + c]) * km;
                if (jg > ig) s = -1e30f;
                acc[r][c] = s;
                mx = fmaxf(mx, s);
            }
            #pragma unroll
            for (int off = 8; off; off >>= 1)
                mx = fmaxf(mx, __shfl_xor_sync(0xffffffffu, mx, off));

            float mnew = fmaxf(mrow[r], mx);
            float scale = __expf(mrow[r] - mnew);   // first iter: exp(-inf)=0
            mrow[r] = mnew;
            float rs = 0.f;
            #pragma unroll
            for (int c = 0; c < 4; ++c) {
                float pe = __expf(acc[r][c] - mnew);
                acc[r][c] = pe;
                rs += pe;
            }
            #pragma unroll
            for (int off = 8; off; off >>= 1)
                rs += __shfl_xor_sync(0xffffffffu, rs, off);
            lrow[r] = lrow[r] * scale + rs;
            #pragma unroll
            for (int c = 0; c < 4; ++c) o[r][c] *= scale;
        }

        // write P to smem (conflict-free: one float4 chunk per thread-row)
        #pragma unroll
        for (int r = 0; r < 4; ++r) {
            float4 pv = make_float4(acc[r][0], acc[r][1], acc[r][2], acc[r][3]);
            *(float4*)(Ps + sw(tr * 4 + r, tc)) = pv;
        }
        __syncthreads();

        // O += P . V  (4x4 per thread, float4 over j on A, float4 over e on B)
        #pragma unroll
        for (int jj = 0; jj < 16; ++jj) {
            float4 a[4];
            #pragma unroll
            for (int r = 0; r < 4; ++r) a[r] = *(const float4*)(Ps + sw(tr * 4 + r, jj));
            #pragma unroll
            for (int js = 0; js < 4; ++js) {
                float4 bv = *(const float4*)(Vs + sw(jj * 4 + js, tc));
                #pragma unroll
                for (int r = 0; r < 4; ++r) {
                    const float* ap = (const float*)&a[r];
                    float av = ap[js];
                    o[r][0] += av * bv.x;
                    o[r][1] += av * bv.y;
                    o[r][2] += av * bv.z;
                    o[r][3] += av * bv.w;
                }
            }
        }
    }

    // epilogue: out = queries + O / l
    #pragma unroll
    for (int r = 0; r < 4; ++r) {
        float linv = 1.0f / lrow[r];
        int ig = i0 + tr * 4 + r;
        size_t goff = ((size_t)((b * Lc + ig) * Hc + h)) * Ec + tc * 4;
        float4 qv = *(const float4*)(q + goff);
        float4 ov = make_float4(qv.x + o[r][0] * linv,
                                qv.y + o[r][1] * linv,
                                qv.z + o[r][2] * linv,
                                qv.w + o[r][3] * linv);
        *(float4*)(out + goff) = ov;
    }
}

// ---------------------------------------------------------------------------

extern "C" void kernel_launch(void* const* d_in, const int* in_sizes, int n_in,
                              void* d_out, int out_size)
{
    const float* q  = (const float*)d_in[0];
    const float* k  = (const float*)d_in[1];
    const float* v  = (const float*)d_in[2];
    const float* qm = (const float*)d_in[3];
    const float* kmsk = (const float*)d_in[4];
    const float* w  = (const float*)d_in[5];
    float* out = (float*)d_out;

    float* qhat;
    cudaGetSymbolAddress((void**)&qhat, g_qhat);

    const int smem2 = (4 * BM * Ec + 2 * BM) * (int)sizeof(float);  // ~66 KB
    cudaFuncSetAttribute(stage2_kernel,
                         cudaFuncAttributeMaxDynamicSharedMemorySize, smem2);

    stage1_kernel<<<Bc * Hc, 1024>>>(q, w, qm, qhat);

    dim3 grid(Lc / BM, Bc * Hc);
    stage2_kernel<<<grid, NTHR, smem2>>>(q, k, v, kmsk, qhat, out);
}

// round 2
// speedup vs baseline: 1.4788x; 1.4788x over previous
#include <cuda_runtime.h>
#include <math.h>
#include <float.h>

#define Bc 4
#define Lc 1024
#define Hc 12
#define Ec 64
#define BM 64
#define BN 64
#define NTILES (Lc / BM)

// scratch (allocation-free rule: __device__ globals)
__device__ float g_qhat[Bc * Lc * Hc * Ec];   // 12 MB
__device__ float g_qn[Bc * Hc * Lc];          // [b][h][l]
__device__ float g_kn[Bc * Hc * Lc];

// XOR-swizzled smem layout at 16B-chunk granularity:
// tile is [64 rows][16 chunks of float4]; returns FLOAT offset.
__device__ __forceinline__ int sw(int row, int c4) {
    return (row * 16 + (c4 ^ (row & 15))) * 4;
}

// ---------------------------------------------------------------------------
// Stage 1: per-(b,h) prefix softmax scan producing qhat[b,i,h,:]
// grid = B*H blocks, 1024 threads
// ---------------------------------------------------------------------------
__global__ void __launch_bounds__(1024) stage1_kernel(
    const float* __restrict__ q, const float* __restrict__ wv,
    const float* __restrict__ q_mask, float* __restrict__ qhat)
{
    int bh = blockIdx.x;
    int b = bh / Hc, h = bh % Hc;

    __shared__ float s_sh[Lc];        // scores, then exp weights
    __shared__ float invZ[Lc];
    __shared__ float gsum[16][Ec];
    __shared__ float w_sh[Ec];
    __shared__ float red[32];
    __shared__ float Msh;

    int tid = threadIdx.x;
    int lane = tid & 31, warp = tid >> 5;

    if (tid < Ec) w_sh[tid] = wv[h * Ec + tid];
    __syncthreads();
    float qm = q_mask[b * Lc];  // q_mask[:, :1] => scalar per batch

    // --- scores s_j = (q_j . w) * qm : one warp per j ---
    for (int j = warp; j < Lc; j += 32) {
        const float* qrow = q + ((size_t)((b * Lc + j) * Hc + h)) * Ec;
        float p = qrow[lane] * w_sh[lane] + qrow[lane + 32] * w_sh[lane + 32];
        #pragma unroll
        for (int o = 16; o; o >>= 1) p += __shfl_xor_sync(0xffffffffu, p, o);
        if (lane == 0) s_sh[j] = p * qm;
    }
    __syncthreads();

    // --- global max over the sequence ---
    float m = s_sh[tid];
    #pragma unroll
    for (int o = 16; o; o >>= 1) m = fmaxf(m, __shfl_xor_sync(0xffffffffu, m, o));
    if (lane == 0) red[warp] = m;
    __syncthreads();
    if (warp == 0) {
        float t = red[lane];
        #pragma unroll
        for (int o = 16; o; o >>= 1) t = fmaxf(t, __shfl_xor_sync(0xffffffffu, t, o));
        if (lane == 0) Msh = t;
    }
    __syncthreads();
    float M = Msh;

    // --- exp weights + inclusive scan of Z ---
    float wexp = __expf(s_sh[tid] - M);
    float sc = wexp;
    #pragma unroll
    for (int o = 1; o < 32; o <<= 1) {
        float t = __shfl_up_sync(0xffffffffu, sc, o);
        if (lane >= o) sc += t;
    }
    if (lane == 31) red[warp] = sc;
    __syncthreads();
    if (warp == 0) {
        float v = red[lane];
        float scn = v;
        #pragma unroll
        for (int o = 1; o < 32; o <<= 1) {
            float t = __shfl_up_sync(0xffffffffu, scn, o);
            if (lane >= o) scn += t;
        }
        red[lane] = scn - v;  // exclusive
    }
    __syncthreads();
    float Z = sc + red[warp];
    s_sh[tid] = wexp;       // safe: each thread overwrites its own element
    invZ[tid] = 1.0f / Z;
    __syncthreads();

    // --- hierarchical vector scan: 16 groups x 64 e-threads ---
    int g = tid >> 6, e = tid & 63;
    const float* qbase = q + (((size_t)(b * Lc)) * Hc + h) * Ec + e;
    float* qhbase = qhat + (((size_t)(b * Lc)) * Hc + h) * Ec + e;
    const size_t rstride = (size_t)Hc * Ec;

    float acc = 0.f;
    int j0 = g * 64;
    #pragma unroll 4
    for (int j = j0; j < j0 + 64; ++j) acc += s_sh[j] * qbase[(size_t)j * rstride];
    gsum[g][e] = acc;
    __syncthreads();
    if (tid < 64) {
        float off = 0.f;
        #pragma unroll
        for (int gg = 0; gg < 16; ++gg) {
            float t = gsum[gg][tid];
            gsum[gg][tid] = off;
            off += t;
        }
    }
    __syncthreads();
    acc = gsum[g][e];
    #pragma unroll 4
    for (int j = j0; j < j0 + 64; ++j) {
        acc += s_sh[j] * qbase[(size_t)j * rstride];
        qhbase[(size_t)j * rstride] = acc * invZ[j];
    }
}

// ---------------------------------------------------------------------------
// Norms: qn = |qhat|^2, kn = |k|^2 per (b,l,h), stored [b][h][l]
// ---------------------------------------------------------------------------
__global__ void __launch_bounds__(256) norms_kernel(
    const float* __restrict__ qhat, const float* __restrict__ k,
    float* __restrict__ qn, float* __restrict__ kn)
{
    int idx = blockIdx.x * 256 + threadIdx.x;     // enumerates (b,l,h)
    if (idx >= Bc * Lc * Hc) return;
    int b = idx / (Lc * Hc);
    int rem = idx % (Lc * Hc);
    int l = rem / Hc, h = rem % Hc;

    const float4* qr = (const float4*)(qhat + (size_t)idx * Ec);
    const float4* kr = (const float4*)(k + (size_t)idx * Ec);
    float sq = 0.f, sk = 0.f;
    #pragma unroll
    for (int i = 0; i < 16; ++i) {
        float4 a = qr[i], c = kr[i];
        sq += a.x * a.x + a.y * a.y + a.z * a.z + a.w * a.w;
        sk += c.x * c.x + c.y * c.y + c.z * c.z + c.w * c.w;
    }
    int o = (b * Hc + h) * Lc + l;
    qn[o] = sq;
    kn[o] = sk;
}

// ---------------------------------------------------------------------------
// Stage 2: causal flash attention, score = (2 qhat.k - |qhat|^2 - |k|^2)*km
// grid = (B*H, NTILES) heavy-first, 128 threads, 8x4 micro-tiles
// ---------------------------------------------------------------------------
__global__ void __launch_bounds__(128, 3) stage2_kernel(
    const float* __restrict__ q, const float* __restrict__ k,
    const float* __restrict__ v, const float* __restrict__ k_mask,
    const float* __restrict__ qhat,
    const float* __restrict__ qn_g, const float* __restrict__ kn_g,
    float* __restrict__ out)
{
    extern __shared__ float smem[];
    float* Qs = smem;                  // 64x64 swizzled
    float* Ks = Qs + BM * Ec;
    float* Vs = Ks + BN * Ec;
    float* Ps = Vs + BN * Ec;
    float* qn_sh = Ps + BM * BN;       // 64
    float* kn_sh = qn_sh + BM;         // 64

    int bh = blockIdx.x;
    int b = bh / Hc, h = bh % Hc;
    int it = NTILES - 1 - (int)blockIdx.y;  // heavy tiles launch first
    int i0 = it * BM;
    int tid = threadIdx.x;
    int tc = tid & 15, tr = tid >> 4;       // tr: 0..7, tc: 0..15
    int row0 = tr * 8;
    float km = k_mask[b * Lc];
    const int nbase = (b * Hc + h) * Lc;

    // load Q tile (qhat) swizzled + qn row
    #pragma unroll
    for (int ii = 0; ii < 8; ++ii) {
        int idx = ii * 128 + tid;
        int row = idx >> 4, c4 = idx & 15;
        const float4 src = *(const float4*)(qhat +
            ((size_t)((b * Lc + i0 + row) * Hc + h)) * Ec + c4 * 4);
        *(float4*)(Qs + sw(row, c4)) = src;
    }
    if (tid < BM) qn_sh[tid] = qn_g[nbase + i0 + tid];

    float o[8][4];
    float mrow[8], lrow[8];
    #pragma unroll
    for (int r = 0; r < 8; ++r) {
        mrow[r] = -INFINITY; lrow[r] = 0.f;
        #pragma unroll
        for (int c = 0; c < 4; ++c) o[r][c] = 0.f;
    }

    for (int jt = 0; jt <= it; ++jt) {
        int j0 = jt * BN;
        __syncthreads();  // protect Ks/Vs reuse (and Qs/qn on first iter)

        // load K, V tiles swizzled + kn row
        #pragma unroll
        for (int ii = 0; ii < 8; ++ii) {
            int idx = ii * 128 + tid;
            int row = idx >> 4, c4 = idx & 15;
            size_t goff = ((size_t)((b * Lc + j0 + row) * Hc + h)) * Ec + c4 * 4;
            *(float4*)(Ks + sw(row, c4)) = *(const float4*)(k + goff);
            *(float4*)(Vs + sw(row, c4)) = *(const float4*)(v + goff);
        }
        if (tid < BN) kn_sh[tid] = kn_g[nbase + j0 + tid];
        __syncthreads();

        // S = Qhat . K^T  (8x4 per thread, float4 over e)
        float acc[8][4];
        #pragma unroll
        for (int r = 0; r < 8; ++r)
            #pragma unroll
            for (int c = 0; c < 4; ++c) acc[r][c] = 0.f;

        #pragma unroll 2
        for (int ee = 0; ee < 16; ++ee) {
            float4 bf[4];
            #pragma unroll
            for (int c = 0; c < 4; ++c) bf[c] = *(const float4*)(Ks + sw(tc * 4 + c, ee));
            #pragma unroll
            for (int r = 0; r < 8; ++r) {
                float4 a = *(const float4*)(Qs + sw(row0 + r, ee));  // broadcast
                #pragma unroll
                for (int c = 0; c < 4; ++c)
                    acc[r][c] += a.x * bf[c].x + a.y * bf[c].y
                               + a.z * bf[c].z + a.w * bf[c].w;
            }
        }

        // scores + online softmax (rows share 16 lanes: same tr)
        #pragma unroll
        for (int r = 0; r < 8; ++r) {
            int ig = i0 + row0 + r;
            float qn = qn_sh[row0 + r];
            float mx = -INFINITY;
            #pragma unroll
            for (int c = 0; c < 4; ++c) {
                int jg = j0 + tc * 4 + c;
                float s = (2.f * acc[r][c] - qn - kn_sh[tc * 4 + c]) * km;
                if (jg > ig) s = -1e30f;
                acc[r][c] = s;
                mx = fmaxf(mx, s);
            }
            #pragma unroll
            for (int off = 8; off; off >>= 1)
                mx = fmaxf(mx, __shfl_xor_sync(0xffffffffu, mx, off));

            float mnew = fmaxf(mrow[r], mx);
            float scale = __expf(mrow[r] - mnew);   // first iter: exp(-inf)=0
            mrow[r] = mnew;
            float rs = 0.f;
            #pragma unroll
            for (int c = 0; c < 4; ++c) {
                float pe = __expf(acc[r][c] - mnew);
                acc[r][c] = pe;
                rs += pe;
            }
            #pragma unroll
            for (int off = 8; off; off >>= 1)
                rs += __shfl_xor_sync(0xffffffffu, rs, off);
            lrow[r] = lrow[r] * scale + rs;
            o[r][0] *= scale; o[r][1] *= scale; o[r][2] *= scale; o[r][3] *= scale;
        }

        // write P to smem
        #pragma unroll
        for (int r = 0; r < 8; ++r) {
            float4 pv = make_float4(acc[r][0], acc[r][1], acc[r][2], acc[r][3]);
            *(float4*)(Ps + sw(row0 + r, tc)) = pv;
        }
        __syncthreads();

        // O += P . V  (8 rows x 4 e-cols per thread)
        #pragma unroll 2
        for (int jj = 0; jj < 16; ++jj) {
            float4 a[8];
            #pragma unroll
            for (int r = 0; r < 8; ++r) a[r] = *(const float4*)(Ps + sw(row0 + r, jj)); // broadcast
            {
                float4 bv = *(const float4*)(Vs + sw(jj * 4 + 0, tc));
                #pragma unroll
                for (int r = 0; r < 8; ++r) {
                    o[r][0] += a[r].x * bv.x; o[r][1] += a[r].x * bv.y;
                    o[r][2] += a[r].x * bv.z; o[r][3] += a[r].x * bv.w;
                }
            }
            {
                float4 bv = *(const float4*)(Vs + sw(jj * 4 + 1, tc));
                #pragma unroll
                for (int r = 0; r < 8; ++r) {
                    o[r][0] += a[r].y * bv.x; o[r][1] += a[r].y * bv.y;
                    o[r][2] += a[r].y * bv.z; o[r][3] += a[r].y * bv.w;
                }
            }
            {
                float4 bv = *(const float4*)(Vs + sw(jj * 4 + 2, tc));
                #pragma unroll
                for (int r = 0; r < 8; ++r) {
                    o[r][0] += a[r].z * bv.x; o[r][1] += a[r].z * bv.y;
                    o[r][2] += a[r].z * bv.z; o[r][3] += a[r].z * bv.w;
                }
            }
            {
                float4 bv = *(const float4*)(Vs + sw(jj * 4 + 3, tc));
                #pragma unroll
                for (int r = 0; r < 8; ++r) {
                    o[r][0] += a[r].w * bv.x; o[r][1] += a[r].w * bv.y;
                    o[r][2] += a[r].w * bv.z; o[r][3] += a[r].w * bv.w;
                }
            }
        }
    }

    // epilogue: out = queries + O / l
    #pragma unroll
    for (int r = 0; r < 8; ++r) {
        float linv = 1.0f / lrow[r];
        int ig = i0 + row0 + r;
        size_t goff = ((size_t)((b * Lc + ig) * Hc + h)) * Ec + tc * 4;
        float4 qv = *(const float4*)(q + goff);
        float4 ov = make_float4(qv.x + o[r][0] * linv,
                                qv.y + o[r][1] * linv,
                                qv.z + o[r][2] * linv,
                                qv.w + o[r][3] * linv);
        *(float4*)(out + goff) = ov;
    }
}

// ---------------------------------------------------------------------------

extern "C" void kernel_launch(void* const* d_in, const int* in_sizes, int n_in,
                              void* d_out, int out_size)
{
    const float* q  = (const float*)d_in[0];
    const float* k  = (const float*)d_in[1];
    const float* v  = (const float*)d_in[2];
    const float* qm = (const float*)d_in[3];
    const float* kmsk = (const float*)d_in[4];
    const float* w  = (const float*)d_in[5];
    float* out = (float*)d_out;

    float *qhat, *qn, *kn;
    cudaGetSymbolAddress((void**)&qhat, g_qhat);
    cudaGetSymbolAddress((void**)&qn, g_qn);
    cudaGetSymbolAddress((void**)&kn, g_kn);

    const int smem2 = (4 * BM * Ec + 2 * BM) * (int)sizeof(float);  // ~66 KB
    cudaFuncSetAttribute(stage2_kernel,
                         cudaFuncAttributeMaxDynamicSharedMemorySize, smem2);

    stage1_kernel<<<Bc * Hc, 1024>>>(q, w, qm, qhat);
    norms_kernel<<<(Bc * Lc * Hc + 255) / 256, 256>>>(qhat, k, qn, kn);

    dim3 grid(Bc * Hc, NTILES);   // y slow => heavy tiles (it = NTILES-1-y) first
    stage2_kernel<<<grid, 128, smem2>>>(q, k, v, kmsk, qhat, qn, kn, out);
}